// round 3
// baseline (speedup 1.0000x reference)
#include <cuda_runtime.h>

// DCT-per-8x8-patch == out(N,64) = X(N,64) @ (C ⊗ C), separable (1024 FMA/strip),
// all coefficients as FFMA immediates. Warp-autonomous smem staging: each warp
// stages 32 strips through its own padded slice; only __syncwarp needed.

#define THREADS 128
#define NWARP   4
#define SLICE4  (32 * 17)   // float4 per warp slice (stride 17 = conflict-free pad)

#define DCT_TABLE(CT)                                                                  \
    const float CT[8][8] = {                                                           \
        {0.353553391f, 0.353553391f, 0.353553391f, 0.353553391f,                       \
         0.353553391f, 0.353553391f, 0.353553391f, 0.353553391f},                      \
        {0.490392640f, 0.415734806f, 0.277785117f, 0.097545161f,                       \
         -0.097545161f, -0.277785117f, -0.415734806f, -0.490392640f},                  \
        {0.461939766f, 0.191341716f, -0.191341716f, -0.461939766f,                     \
         -0.461939766f, -0.191341716f, 0.191341716f, 0.461939766f},                    \
        {0.415734806f, -0.097545161f, -0.490392640f, -0.277785117f,                    \
         0.277785117f, 0.490392640f, 0.097545161f, -0.415734806f},                     \
        {0.353553391f, -0.353553391f, -0.353553391f, 0.353553391f,                     \
         0.353553391f, -0.353553391f, -0.353553391f, 0.353553391f},                    \
        {0.277785117f, -0.490392640f, 0.097545161f, 0.415734806f,                      \
         -0.415734806f, -0.097545161f, 0.490392640f, -0.277785117f},                   \
        {0.191341716f, -0.461939766f, 0.461939766f, -0.191341716f,                     \
         -0.191341716f, 0.461939766f, -0.461939766f, 0.191341716f},                    \
        {0.097545161f, -0.277785117f, 0.415734806f, -0.490392640f,                     \
         0.490392640f, -0.415734806f, 0.277785117f, -0.097545161f}};

__global__ __launch_bounds__(THREADS, 6)
void dct_main_kernel(const float4* __restrict__ in4, float4* __restrict__ out4)
{
    __shared__ float4 sm[NWARP * SLICE4];
    const int lane = threadIdx.x & 31;
    const int w    = threadIdx.x >> 5;
    // warp's 32 strips start at float4 index:
    const size_t wbase = (size_t)blockIdx.x * (THREADS * 16) + (size_t)w * (32 * 16);
    float4* s = sm + w * SLICE4;
    // coalesced<->padded mapping: float4 f in warp region: strip=f>>4, chunk=f&15
    const int sts_off = (lane >> 4) * 17 + (lane & 15);

    // Phase 1: gmem -> regs (MLP=16) -> padded smem. Coalesced 512B per instr.
    {
        float4 t[16];
#pragma unroll
        for (int k = 0; k < 16; ++k) t[k] = in4[wbase + k * 32 + lane];
#pragma unroll
        for (int k = 0; k < 16; ++k) s[(2 * k) * 17 + sts_off] = t[k];
    }
    __syncwarp();

    // Phase 2: own strip smem -> regs (conflict-free), transform, rows -> smem.
    float x[64];
    float4* sp = s + lane * 17;
#pragma unroll
    for (int k = 0; k < 16; ++k) {
        float4 v = sp[k];
        x[4 * k + 0] = v.x; x[4 * k + 1] = v.y;
        x[4 * k + 2] = v.z; x[4 * k + 3] = v.w;
    }

    DCT_TABLE(CT);
    // Stage 1 (in place): x[u*8+j] <- sum_v x[u*8+v] * CT[v][j]
#pragma unroll
    for (int u = 0; u < 8; ++u) {
        float t[8];
#pragma unroll
        for (int j = 0; j < 8; ++j) {
            float a = x[u * 8 + 0] * CT[0][j];
#pragma unroll
            for (int v = 1; v < 8; ++v) a = fmaf(x[u * 8 + v], CT[v][j], a);
            t[j] = a;
        }
#pragma unroll
        for (int j = 0; j < 8; ++j) x[u * 8 + j] = t[j];
    }
    // Stage 2: row i streamed straight to smem (no y copy, no x write-back)
#pragma unroll
    for (int i = 0; i < 8; ++i) {
        float o[8];
#pragma unroll
        for (int j = 0; j < 8; ++j) {
            float a = x[0 * 8 + j] * CT[0][i];
#pragma unroll
            for (int u = 1; u < 8; ++u) a = fmaf(x[u * 8 + j], CT[u][i], a);
            o[j] = a;
        }
        sp[2 * i + 0] = make_float4(o[0], o[1], o[2], o[3]);
        sp[2 * i + 1] = make_float4(o[4], o[5], o[6], o[7]);
    }
    __syncwarp();

    // Phase 3: padded smem -> gmem, coalesced.
#pragma unroll
    for (int k = 0; k < 16; ++k)
        out4[wbase + k * 32 + lane] = s[(2 * k) * 17 + sts_off];
}

// Tail (strip count not divisible by 128): direct per-thread path, tiny.
__global__ void dct_tail_kernel(const float4* __restrict__ in4,
                                float4* __restrict__ out4,
                                int first_strip, int nstrips)
{
    int strip = first_strip + blockIdx.x * blockDim.x + threadIdx.x;
    if (strip >= nstrips) return;
    float x[64];
    const float4* ip = in4 + (size_t)strip * 16;
#pragma unroll
    for (int k = 0; k < 16; ++k) {
        float4 v = ip[k];
        x[4 * k + 0] = v.x; x[4 * k + 1] = v.y;
        x[4 * k + 2] = v.z; x[4 * k + 3] = v.w;
    }
    DCT_TABLE(CT);
#pragma unroll
    for (int u = 0; u < 8; ++u) {
        float t[8];
#pragma unroll
        for (int j = 0; j < 8; ++j) {
            float a = x[u * 8 + 0] * CT[0][j];
#pragma unroll
            for (int v = 1; v < 8; ++v) a = fmaf(x[u * 8 + v], CT[v][j], a);
            t[j] = a;
        }
#pragma unroll
        for (int j = 0; j < 8; ++j) x[u * 8 + j] = t[j];
    }
    float4* op = out4 + (size_t)strip * 16;
#pragma unroll
    for (int i = 0; i < 8; ++i) {
        float o[8];
#pragma unroll
        for (int j = 0; j < 8; ++j) {
            float a = x[0 * 8 + j] * CT[0][i];
#pragma unroll
            for (int u = 1; u < 8; ++u) a = fmaf(x[u * 8 + j], CT[u][i], a);
            o[j] = a;
        }
        op[2 * i + 0] = make_float4(o[0], o[1], o[2], o[3]);
        op[2 * i + 1] = make_float4(o[4], o[5], o[6], o[7]);
    }
}

extern "C" void kernel_launch(void* const* d_in, const int* in_sizes, int n_in,
                              void* d_out, int out_size)
{
    const float4* in4 = (const float4*)d_in[0];  // (8,3,1024,1024) fp32 contiguous
    float4* out4      = (float4*)d_out;

    int nstrips = in_sizes[0] / 64;              // 393216 on the bench shape
    int nfull   = nstrips / THREADS;
    if (nfull > 0)
        dct_main_kernel<<<nfull, THREADS>>>(in4, out4);
    int rem = nstrips - nfull * THREADS;
    if (rem > 0)
        dct_tail_kernel<<<(rem + 127) / 128, 128>>>(in4, out4, nfull * THREADS, nstrips);
}

// round 4
// speedup vs baseline: 1.3345x; 1.3345x over previous
#include <cuda_runtime.h>
#include <cstdint>

// DCT per 8x8 patch == out(N,64) = X(N,64) @ (C ⊗ C), separable two-pass
// (1024 FMA/strip), coefficients as FFMA immediates. cp.async double-buffered
// pipeline: tile n+1's gmem->smem copies overlap tile n's compute+store.

#define THREADS     128
#define TILE_STRIPS 128
#define TILE_F4     (TILE_STRIPS * 16)   // float4 per tile in gmem
#define PAD_F4      (TILE_STRIPS * 17)   // padded float4 per tile in smem
#define NBUF        2

#define DCT_TABLE(CT)                                                                  \
    const float CT[8][8] = {                                                           \
        {0.353553391f, 0.353553391f, 0.353553391f, 0.353553391f,                       \
         0.353553391f, 0.353553391f, 0.353553391f, 0.353553391f},                      \
        {0.490392640f, 0.415734806f, 0.277785117f, 0.097545161f,                       \
         -0.097545161f, -0.277785117f, -0.415734806f, -0.490392640f},                  \
        {0.461939766f, 0.191341716f, -0.191341716f, -0.461939766f,                     \
         -0.461939766f, -0.191341716f, 0.191341716f, 0.461939766f},                    \
        {0.415734806f, -0.097545161f, -0.490392640f, -0.277785117f,                    \
         0.277785117f, 0.490392640f, 0.097545161f, -0.415734806f},                     \
        {0.353553391f, -0.353553391f, -0.353553391f, 0.353553391f,                     \
         0.353553391f, -0.353553391f, -0.353553391f, 0.353553391f},                    \
        {0.277785117f, -0.490392640f, 0.097545161f, 0.415734806f,                      \
         -0.415734806f, -0.097545161f, 0.490392640f, -0.277785117f},                   \
        {0.191341716f, -0.461939766f, 0.461939766f, -0.191341716f,                     \
         -0.191341716f, 0.461939766f, -0.461939766f, 0.191341716f},                    \
        {0.097545161f, -0.277785117f, 0.415734806f, -0.490392640f,                     \
         0.490392640f, -0.415734806f, 0.277785117f, -0.097545161f}};

__device__ __forceinline__ void cp_async16(float4* smem_dst, const float4* gsrc)
{
    uint32_t s = (uint32_t)__cvta_generic_to_shared(smem_dst);
    asm volatile("cp.async.cg.shared.global [%0], [%1], 16;\n" :: "r"(s), "l"(gsrc));
}
__device__ __forceinline__ void cp_commit()  { asm volatile("cp.async.commit_group;\n" ::: "memory"); }
__device__ __forceinline__ void cp_wait1()   { asm volatile("cp.async.wait_group 1;\n" ::: "memory"); }

__global__ __launch_bounds__(THREADS)
void dct_pipe_kernel(const float4* __restrict__ in4, float4* __restrict__ out4,
                     int ntiles)
{
    __shared__ float4 sm[NBUF * PAD_F4];
    const int t    = threadIdx.x;
    const int trow = t >> 4;      // coalesced slot -> strip row
    const int tcol = t & 15;
    const int pad_off = trow * 17 + tcol;   // + (k*8)*17 per chunk k

    const int stride = gridDim.x;
    int tile = blockIdx.x;

    // Prologue: prefetch first tile into buffer 0.
    if (tile < ntiles) {
        const float4* g = in4 + (size_t)tile * TILE_F4;
#pragma unroll
        for (int k = 0; k < 16; ++k)
            cp_async16(&sm[(k * 8) * 17 + pad_off], &g[k * THREADS + t]);
    }
    cp_commit();

    int buf = 0;
    for (int i = tile; i < ntiles; i += stride) {
        // Prefetch next tile into the spare buffer (overlaps this tile's compute).
        int nxt = i + stride;
        if (nxt < ntiles) {
            const float4* g = in4 + (size_t)nxt * TILE_F4;
            float4* d = &sm[(buf ^ 1) * PAD_F4];
#pragma unroll
            for (int k = 0; k < 16; ++k)
                cp_async16(&d[(k * 8) * 17 + pad_off], &g[k * THREADS + t]);
        }
        cp_commit();          // always commit (keeps wait_group accounting correct)
        cp_wait1();           // current tile's copies complete
        __syncthreads();

        float4* s  = &sm[buf * PAD_F4];
        float4* sp = s + t * 17;

        // Own strip: smem -> regs (conflict-free via stride-17 pad).
        float x[64];
#pragma unroll
        for (int k = 0; k < 16; ++k) {
            float4 v = sp[k];
            x[4 * k + 0] = v.x; x[4 * k + 1] = v.y;
            x[4 * k + 2] = v.z; x[4 * k + 3] = v.w;
        }

        DCT_TABLE(CT);
        // Stage 1 (in place): x[u*8+j] <- sum_v x[u*8+v] * CT[v][j]
#pragma unroll
        for (int u = 0; u < 8; ++u) {
            float tr[8];
#pragma unroll
            for (int j = 0; j < 8; ++j) {
                float a = x[u * 8 + 0] * CT[0][j];
#pragma unroll
                for (int v = 1; v < 8; ++v) a = fmaf(x[u * 8 + v], CT[v][j], a);
                tr[j] = a;
            }
#pragma unroll
            for (int j = 0; j < 8; ++j) x[u * 8 + j] = tr[j];
        }
        // Stage 2: row i streamed straight back to smem.
#pragma unroll
        for (int i2 = 0; i2 < 8; ++i2) {
            float o[8];
#pragma unroll
            for (int j = 0; j < 8; ++j) {
                float a = x[0 * 8 + j] * CT[0][i2];
#pragma unroll
                for (int u = 1; u < 8; ++u) a = fmaf(x[u * 8 + j], CT[u][i2], a);
                o[j] = a;
            }
            sp[2 * i2 + 0] = make_float4(o[0], o[1], o[2], o[3]);
            sp[2 * i2 + 1] = make_float4(o[4], o[5], o[6], o[7]);
        }
        __syncthreads();

        // Coalesced smem -> gmem.
        float4* go = out4 + (size_t)i * TILE_F4;
#pragma unroll
        for (int k = 0; k < 16; ++k)
            go[k * THREADS + t] = s[(k * 8) * 17 + pad_off];
        __syncthreads();      // buffer free before it becomes a prefetch target

        buf ^= 1;
    }
}

// Tail (strip count not divisible by 128): direct per-thread path, tiny.
__global__ void dct_tail_kernel(const float4* __restrict__ in4,
                                float4* __restrict__ out4,
                                int first_strip, int nstrips)
{
    int strip = first_strip + blockIdx.x * blockDim.x + threadIdx.x;
    if (strip >= nstrips) return;
    float x[64];
    const float4* ip = in4 + (size_t)strip * 16;
#pragma unroll
    for (int k = 0; k < 16; ++k) {
        float4 v = ip[k];
        x[4 * k + 0] = v.x; x[4 * k + 1] = v.y;
        x[4 * k + 2] = v.z; x[4 * k + 3] = v.w;
    }
    DCT_TABLE(CT);
#pragma unroll
    for (int u = 0; u < 8; ++u) {
        float tr[8];
#pragma unroll
        for (int j = 0; j < 8; ++j) {
            float a = x[u * 8 + 0] * CT[0][j];
#pragma unroll
            for (int v = 1; v < 8; ++v) a = fmaf(x[u * 8 + v], CT[v][j], a);
            tr[j] = a;
        }
#pragma unroll
        for (int j = 0; j < 8; ++j) x[u * 8 + j] = tr[j];
    }
    float4* op = out4 + (size_t)strip * 16;
#pragma unroll
    for (int i = 0; i < 8; ++i) {
        float o[8];
#pragma unroll
        for (int j = 0; j < 8; ++j) {
            float a = x[0 * 8 + j] * CT[0][i];
#pragma unroll
            for (int u = 1; u < 8; ++u) a = fmaf(x[u * 8 + j], CT[u][i], a);
            o[j] = a;
        }
        op[2 * i + 0] = make_float4(o[0], o[1], o[2], o[3]);
        op[2 * i + 1] = make_float4(o[4], o[5], o[6], o[7]);
    }
}

extern "C" void kernel_launch(void* const* d_in, const int* in_sizes, int n_in,
                              void* d_out, int out_size)
{
    const float4* in4 = (const float4*)d_in[0];  // (8,3,1024,1024) fp32 contiguous
    float4* out4      = (float4*)d_out;

    int nstrips = in_sizes[0] / 64;              // 393216 on bench shape
    int ntiles  = nstrips / TILE_STRIPS;

    if (ntiles > 0) {
        int nsm = 148;
        cudaDeviceGetAttribute(&nsm, cudaDevAttrMultiProcessorCount, 0);
        int grid = 3 * nsm;                      // exactly resident (3 CTAs/SM by smem)
        if (grid > ntiles) grid = ntiles;
        dct_pipe_kernel<<<grid, THREADS>>>(in4, out4, ntiles);
    }
    int rem = nstrips - ntiles * TILE_STRIPS;
    if (rem > 0)
        dct_tail_kernel<<<(rem + 127) / 128, 128>>>(in4, out4,
                                                    ntiles * TILE_STRIPS, nstrips);
}